// round 1
// baseline (speedup 1.0000x reference)
#include <cuda_runtime.h>
#include <math.h>

#define BB   2
#define CC   256
#define LL   4096
#define DSZ  16
#define NCH  64
#define CLN  64          // LL / NCH
#define NPOS (BB*LL)     // 8192

// ---------------- scratch (static device globals; no allocation) ----------------
__device__ float g_t[NPOS*CC];          // running activation (B,L,C)
__device__ float g_xz[NPOS*2*CC];       // in-proj output (B,L,512)
__device__ float g_seq[NPOS*CC];        // conv+silu+flip output (B,L,C)
__device__ float g_dbl[NPOS*48];        // xproj output
__device__ float g_dt[NPOS*CC];         // softplus(dt)
__device__ float g_r[NPOS*CC];          // exp(-dt)
__device__ float g_y[NPOS*CC];          // scan output
__device__ float g_y2[NPOS*CC];         // gated LN output / postln tmp
__device__ float g_rowm[NPOS];
__device__ float g_rowrs[NPOS];
__device__ float g_gw[2*CC*CC];         // ln-folded in_w (512x256)
__device__ float g_sgw[2*CC];
__device__ float g_bw[2*CC];
__device__ float g_A[CC*DSZ];
__device__ int   g_fast;
__device__ float g_P[BB*CC*NCH*DSZ];
__device__ float g_hend[BB*CC*NCH*DSZ];
__device__ float g_hst[BB*CC*NCH*DSZ];

// ---------------- helpers ----------------
__device__ __forceinline__ void blockMeanRstd256(float v, float& m, float& rs) {
    float s = v, s2 = v * v;
    #pragma unroll
    for (int o = 16; o; o >>= 1) {
        s  += __shfl_xor_sync(0xffffffffu, s,  o);
        s2 += __shfl_xor_sync(0xffffffffu, s2, o);
    }
    __shared__ float sm[8], sm2[8];
    int w = threadIdx.x >> 5, lane = threadIdx.x & 31;
    if (lane == 0) { sm[w] = s; sm2[w] = s2; }
    __syncthreads();
    if (w == 0) {
        float a = (lane < 8) ? sm[lane]  : 0.f;
        float b = (lane < 8) ? sm2[lane] : 0.f;
        #pragma unroll
        for (int o = 4; o; o >>= 1) {
            a += __shfl_xor_sync(0xffffffffu, a, o);
            b += __shfl_xor_sync(0xffffffffu, b, o);
        }
        if (lane == 0) { sm[0] = a; sm2[0] = b; }
    }
    __syncthreads();
    m  = sm[0] * (1.f / CC);
    rs = rsqrtf(sm2[0] * (1.f / CC) - m * m + 1e-5f);
}

// ---------------- initial transpose: x(B,C,D,H,W) -> t(B, (h,w,d), C) ----------------
__global__ void k_init_tr(const float* __restrict__ x) {
    __shared__ float tile[32][33];
    int b = blockIdx.z >> 4, d = blockIdx.z & 15;
    int hw0 = blockIdx.x * 32, c0 = blockIdx.y * 32;
    int tx = threadIdx.x, ty = threadIdx.y;
    tile[ty][tx] = x[((size_t)(b*CC + c0 + ty) * 16 + d) * 256 + hw0 + tx];
    __syncthreads();
    g_t[((size_t)b*LL + (size_t)(hw0 + ty) * 16 + d) * CC + c0 + tx] = tile[tx][ty];
}

// ---------------- per-row LN stats over C ----------------
__global__ void k_rowstats() {
    int warp = threadIdx.x >> 5, lane = threadIdx.x & 31;
    int p = blockIdx.x * 8 + warp;
    const float* row = g_t + (size_t)p * CC;
    float s = 0.f, s2 = 0.f;
    #pragma unroll
    for (int j = lane; j < CC; j += 32) { float v = row[j]; s += v; s2 += v * v; }
    #pragma unroll
    for (int o = 16; o; o >>= 1) {
        s  += __shfl_xor_sync(0xffffffffu, s,  o);
        s2 += __shfl_xor_sync(0xffffffffu, s2, o);
    }
    if (lane == 0) {
        float m = s * (1.f / CC);
        float var = s2 * (1.f / CC) - m * m;
        g_rowm[p] = m;
        g_rowrs[p] = rsqrtf(var + 1e-5f);
    }
}

// ---------------- per-layer prep: fold LN gamma into in_w ----------------
__global__ void k_prep_inw(const float* __restrict__ inw,
                           const float* __restrict__ g,
                           const float* __restrict__ bvec) {
    int n = blockIdx.x, k = threadIdx.x;
    float w  = inw[n * CC + k];
    float gw = w * g[k];
    g_gw[n * CC + k] = gw;
    float bw = w * bvec[k];
    float sg = gw, sb = bw;
    #pragma unroll
    for (int o = 16; o; o >>= 1) {
        sg += __shfl_xor_sync(0xffffffffu, sg, o);
        sb += __shfl_xor_sync(0xffffffffu, sb, o);
    }
    __shared__ float smA[8], smB[8];
    if ((k & 31) == 0) { smA[k >> 5] = sg; smB[k >> 5] = sb; }
    __syncthreads();
    if (k == 0) {
        float a = 0.f, b2 = 0.f;
        #pragma unroll
        for (int i = 0; i < 8; i++) { a += smA[i]; b2 += smB[i]; }
        g_sgw[n] = a; g_bw[n] = b2;
    }
}

// ---------------- per-layer prep: A matrix, detect A_n == -(n+1) ----------------
__global__ void k_prep_A(const float* __restrict__ alog) {
    int c = threadIdx.x;
    __shared__ int ok;
    if (c == 0) ok = 1;
    __syncthreads();
    bool good = true;
    #pragma unroll
    for (int n = 0; n < DSZ; n++) {
        float a = -expf(alog[c * DSZ + n]);
        g_A[c * DSZ + n] = a;
        if (fabsf(a + (float)(n + 1)) > 1e-3f) good = false;
    }
    if (!good) atomicAnd(&ok, 0);
    __syncthreads();
    if (c == 0) g_fast = ok;
}

// ---------------- generic fp32 SGEMM: C[M,N] = A[M,K] * B[N,K]^T, fused epilogues ----------------
// mode 0: plain      mode 1: LN-fold (g_rowm/g_rowrs/g_sgw/g_bw)
// mode 2: +cbias, softplus -> C, exp(-softplus) -> C2
// mode 3: residual add (resid same layout as C)
__launch_bounds__(256)
__global__ void k_gemm(const float* __restrict__ A, int lda,
                       const float* __restrict__ B, int ldb,
                       float* __restrict__ C, int ldc,
                       int M, int N, int K, int mode,
                       const float* __restrict__ cbias,
                       float* __restrict__ C2,
                       const float* __restrict__ resid) {
    __shared__ __align__(16) float As[8][128];
    __shared__ __align__(16) float Bs[8][128];
    int tid = threadIdx.x;
    int row0 = blockIdx.y * 128, col0 = blockIdx.x * 128;
    int lr = tid >> 1, seg = (tid & 1) * 4;
    int mBase = (tid >> 4) * 8, nBase = (tid & 15) * 8;

    float acc[8][8];
    #pragma unroll
    for (int i = 0; i < 8; i++)
        #pragma unroll
        for (int j = 0; j < 8; j++) acc[i][j] = 0.f;

    for (int k0 = 0; k0 < K; k0 += 8) {
        {
            int r = row0 + lr;
            float4 v = make_float4(0.f, 0.f, 0.f, 0.f);
            if (r < M) v = *(const float4*)(A + (size_t)r * lda + k0 + seg);
            As[seg + 0][lr] = v.x; As[seg + 1][lr] = v.y;
            As[seg + 2][lr] = v.z; As[seg + 3][lr] = v.w;
        }
        {
            int r = col0 + lr;
            float4 v = make_float4(0.f, 0.f, 0.f, 0.f);
            if (r < N) v = *(const float4*)(B + (size_t)r * ldb + k0 + seg);
            Bs[seg + 0][lr] = v.x; Bs[seg + 1][lr] = v.y;
            Bs[seg + 2][lr] = v.z; Bs[seg + 3][lr] = v.w;
        }
        __syncthreads();
        #pragma unroll
        for (int kk = 0; kk < 8; kk++) {
            float a[8], b[8];
            *(float4*)(a)     = *(const float4*)&As[kk][mBase];
            *(float4*)(a + 4) = *(const float4*)&As[kk][mBase + 4];
            *(float4*)(b)     = *(const float4*)&Bs[kk][nBase];
            *(float4*)(b + 4) = *(const float4*)&Bs[kk][nBase + 4];
            #pragma unroll
            for (int i = 0; i < 8; i++)
                #pragma unroll
                for (int j = 0; j < 8; j++) acc[i][j] += a[i] * b[j];
        }
        __syncthreads();
    }

    #pragma unroll
    for (int i = 0; i < 8; i++) {
        int r = row0 + mBase + i;
        if (r >= M) continue;
        float rm = 0.f, rr = 0.f;
        if (mode == 1) { rm = g_rowm[r]; rr = g_rowrs[r]; }
        #pragma unroll
        for (int j = 0; j < 8; j++) {
            int c = col0 + nBase + j;
            if (c >= N) continue;
            float v = acc[i][j];
            if (mode == 1) {
                v = rr * (v - rm * g_sgw[c]) + g_bw[c];
            } else if (mode == 2) {
                float tt = v + cbias[c];
                float sp = fmaxf(tt, 0.f) + log1pf(expf(-fabsf(tt)));
                C2[(size_t)r * ldc + c] = expf(-sp);
                v = sp;
            } else if (mode == 3) {
                v += resid[(size_t)r * ldc + c];
            }
            C[(size_t)r * ldc + c] = v;
        }
    }
}

// ---------------- depthwise 3x3x3 conv + bias + SiLU + flip -> seq ----------------
__global__ void k_conv(const float* __restrict__ convw,
                       const float* __restrict__ convb, int ori) {
    int bidx = blockIdx.x;
    int b = bidx >> 8, h = (bidx >> 4) & 15, w = bidx & 15;
    int c = threadIdx.x;
    __shared__ float ws[256 * 27];
    for (int i = threadIdx.x; i < 256 * 27; i += 256) ws[i] = convw[i];
    __syncthreads();
    float wr[27];
    #pragma unroll
    for (int j = 0; j < 27; j++) wr[j] = ws[c * 27 + j];
    float bias = convb[c];
    int fh = (ori & 1) ? 15 - h : h;
    int fw = (ori & 2) ? 15 - w : w;
    for (int d = 0; d < 16; d++) {
        float acc = bias;
        #pragma unroll
        for (int s1 = 0; s1 < 3; s1++) {
            int hh = h + s1 - 1; if (hh < 0 || hh > 15) continue;
            #pragma unroll
            for (int s2 = 0; s2 < 3; s2++) {
                int ww = w + s2 - 1; if (ww < 0 || ww > 15) continue;
                #pragma unroll
                for (int s3 = 0; s3 < 3; s3++) {
                    int dd = d + s3 - 1; if (dd < 0 || dd > 15) continue;
                    int p = b * LL + (hh * 16 + ww) * 16 + dd;
                    acc += wr[s1 * 9 + s2 * 3 + s3] * g_xz[(size_t)p * 512 + c];
                }
            }
        }
        float sv = acc / (1.f + expf(-acc));
        int fd = (ori & 4) ? 15 - d : d;
        int dl = (fh * 16 + fw) * 16 + fd;
        g_seq[((size_t)b * LL + dl) * CC + c] = sv;
    }
}

// ---------------- chunked selective scan: phase A (local products / end states) ----------------
__global__ void k_scanA() {
    int c = blockIdx.y * 128 + threadIdx.x;
    int ch = blockIdx.x, b = blockIdx.z;
    __shared__ float Bsm[CLN][DSZ];
    for (int i = threadIdx.x; i < CLN * DSZ; i += 128) {
        int t = i >> 4, n = i & 15;
        Bsm[t][n] = g_dbl[((size_t)b * LL + ch * CLN + t) * 48 + 16 + n];
    }
    __syncthreads();
    float h[DSZ], P[DSZ];
    #pragma unroll
    for (int n = 0; n < DSZ; n++) { h[n] = 0.f; P[n] = 1.f; }
    size_t base = ((size_t)b * LL + ch * CLN) * CC + c;
    if (g_fast) {
        for (int t = 0; t < CLN; t++) {
            float rv = g_r[base], dtv = g_dt[base], xv = g_seq[base];
            base += CC;
            float dtx = dtv * xv;
            float rp = rv;
            #pragma unroll
            for (int n = 0; n < DSZ; n++) {
                h[n] = rp * h[n] + dtx * Bsm[t][n];
                P[n] *= rp;
                rp *= rv;
            }
        }
    } else {
        for (int t = 0; t < CLN; t++) {
            float dtv = g_dt[base], xv = g_seq[base];
            base += CC;
            float dtx = dtv * xv;
            #pragma unroll
            for (int n = 0; n < DSZ; n++) {
                float dA = __expf(dtv * g_A[c * DSZ + n]);
                h[n] = dA * h[n] + dtx * Bsm[t][n];
                P[n] *= dA;
            }
        }
    }
    size_t off = (((size_t)(b * CC + c)) * NCH + ch) * DSZ;
    #pragma unroll
    for (int n = 0; n < DSZ; n++) { g_hend[off + n] = h[n]; g_P[off + n] = P[n]; }
}

// ---------------- phase B: sequential chunk combine ----------------
__global__ void k_scanB() {
    int idx = blockIdx.x * 256 + threadIdx.x;          // (b*CC+c)*16 + n, 8192 total
    if (idx >= BB * CC * DSZ) return;
    int n = idx & 15, bc = idx >> 4;
    float H = 0.f;
    size_t base = (size_t)bc * NCH * DSZ + n;
    for (int k = 0; k < NCH; k++) {
        g_hst[base + (size_t)k * DSZ] = H;
        H = g_P[base + (size_t)k * DSZ] * H + g_hend[base + (size_t)k * DSZ];
    }
}

// ---------------- phase C: replay with correct init states, produce y ----------------
__global__ void k_scanC(const float* __restrict__ Dv) {
    int c = blockIdx.y * 128 + threadIdx.x;
    int ch = blockIdx.x, b = blockIdx.z;
    __shared__ float Bsm[CLN][DSZ];
    __shared__ float Csm[CLN][DSZ];
    for (int i = threadIdx.x; i < CLN * DSZ; i += 128) {
        int t = i >> 4, n = i & 15;
        size_t rb = ((size_t)b * LL + ch * CLN + t) * 48;
        Bsm[t][n] = g_dbl[rb + 16 + n];
        Csm[t][n] = g_dbl[rb + 32 + n];
    }
    __syncthreads();
    float h[DSZ];
    size_t off = (((size_t)(b * CC + c)) * NCH + ch) * DSZ;
    #pragma unroll
    for (int n = 0; n < DSZ; n++) h[n] = g_hst[off + n];
    float Dc = Dv[c];
    size_t base = ((size_t)b * LL + ch * CLN) * CC + c;
    if (g_fast) {
        for (int t = 0; t < CLN; t++) {
            float rv = g_r[base], dtv = g_dt[base], xv = g_seq[base];
            float dtx = dtv * xv;
            float y = 0.f;
            float rp = rv;
            #pragma unroll
            for (int n = 0; n < DSZ; n++) {
                h[n] = rp * h[n] + dtx * Bsm[t][n];
                y += h[n] * Csm[t][n];
                rp *= rv;
            }
            g_y[base] = y + Dc * xv;
            base += CC;
        }
    } else {
        for (int t = 0; t < CLN; t++) {
            float dtv = g_dt[base], xv = g_seq[base];
            float dtx = dtv * xv;
            float y = 0.f;
            #pragma unroll
            for (int n = 0; n < DSZ; n++) {
                float dA = __expf(dtv * g_A[c * DSZ + n]);
                h[n] = dA * h[n] + dtx * Bsm[t][n];
                y += h[n] * Csm[t][n];
            }
            g_y[base] = y + Dc * xv;
            base += CC;
        }
    }
}

// ---------------- unflip + output LN + SiLU gate ----------------
__global__ void k_gate(const float* __restrict__ og,
                       const float* __restrict__ ob, int ori) {
    int p = blockIdx.x, c = threadIdx.x;
    int b = p >> 12, l = p & 4095;
    int h = l >> 8, w = (l >> 4) & 15, d = l & 15;
    if (ori & 1) h = 15 - h;
    if (ori & 2) w = 15 - w;
    if (ori & 4) d = 15 - d;
    int ls = (h << 8) | (w << 4) | d;
    float v = g_y[((size_t)((b << 12) | ls)) * CC + c];
    float m, rs;
    blockMeanRstd256(v, m, rs);
    float z = g_xz[(size_t)p * 512 + 256 + c];
    float sz = z / (1.f + expf(-z));
    g_y2[(size_t)p * CC + c] = ((v - m) * rs * og[c] + ob[c]) * sz;
}

// ---------------- final post-LN ----------------
__global__ void k_postln(const float* __restrict__ g, const float* __restrict__ bvec) {
    int p = blockIdx.x, c = threadIdx.x;
    float v = g_t[(size_t)p * CC + c];
    float m, rs;
    blockMeanRstd256(v, m, rs);
    g_y2[(size_t)p * CC + c] = (v - m) * rs * g[c] + bvec[c];
}

// ---------------- final transpose: tmp(B,(h,w,d),C) -> out(B,C,D,H,W) ----------------
__global__ void k_final_tr(float* __restrict__ out) {
    __shared__ float tile[32][33];
    int b = blockIdx.z >> 4, d = blockIdx.z & 15;
    int hw0 = blockIdx.x * 32, c0 = blockIdx.y * 32;
    int tx = threadIdx.x, ty = threadIdx.y;
    tile[ty][tx] = g_y2[((size_t)b * LL + (size_t)(hw0 + ty) * 16 + d) * CC + c0 + tx];
    __syncthreads();
    out[((size_t)(b * CC + c0 + ty) * 16 + d) * 256 + hw0 + tx] = tile[tx][ty];
}

// ---------------- host ----------------
extern "C" void kernel_launch(void* const* d_in, const int* in_sizes, int n_in,
                              void* d_out, int out_size) {
    const float* x       = (const float*)d_in[0];
    const float* in_w    = (const float*)d_in[1];
    const float* conv_w  = (const float*)d_in[2];
    const float* conv_b  = (const float*)d_in[3];
    const float* xproj_w = (const float*)d_in[4];
    const float* dt_w    = (const float*)d_in[5];
    const float* dt_b    = (const float*)d_in[6];
    const float* A_log   = (const float*)d_in[7];
    const float* D_skip  = (const float*)d_in[8];
    const float* on_g    = (const float*)d_in[9];
    const float* on_b    = (const float*)d_in[10];
    const float* out_w   = (const float*)d_in[11];
    const float* ln1_g   = (const float*)d_in[12];
    const float* ln1_b   = (const float*)d_in[13];
    const float* post_g  = (const float*)d_in[14];
    const float* post_b  = (const float*)d_in[15];
    float* out = (float*)d_out;

    void *p_t, *p_xz, *p_seq, *p_dbl, *p_dt, *p_r, *p_y2, *p_gw;
    cudaGetSymbolAddress(&p_t,   g_t);
    cudaGetSymbolAddress(&p_xz,  g_xz);
    cudaGetSymbolAddress(&p_seq, g_seq);
    cudaGetSymbolAddress(&p_dbl, g_dbl);
    cudaGetSymbolAddress(&p_dt,  g_dt);
    cudaGetSymbolAddress(&p_r,   g_r);
    cudaGetSymbolAddress(&p_y2,  g_y2);
    cudaGetSymbolAddress(&p_gw,  g_gw);

    k_init_tr<<<dim3(8, 8, 32), dim3(32, 32)>>>(x);

    for (int i = 0; i < 4; i++) {
        int ori = i;  // i % 8
        k_prep_inw<<<512, 256>>>(in_w + (size_t)i * 512 * 256,
                                 ln1_g + i * 256, ln1_b + i * 256);
        k_prep_A<<<1, 256>>>(A_log + (size_t)i * 256 * 16);
        k_rowstats<<<NPOS / 8, 256>>>();
        // in-proj with LN folded: (8192 x 512) = t(8192x256) * gw(512x256)^T
        k_gemm<<<dim3(4, 64), 256>>>((const float*)p_t, 256, (const float*)p_gw, 256,
                                     (float*)p_xz, 512, NPOS, 512, 256, 1,
                                     nullptr, nullptr, nullptr);
        k_conv<<<BB * 256, 256>>>(conv_w + (size_t)i * 256 * 27, conv_b + i * 256, ori);
        // xproj: (8192 x 48)
        k_gemm<<<dim3(1, 64), 256>>>((const float*)p_seq, 256,
                                     xproj_w + (size_t)i * 48 * 256, 256,
                                     (float*)p_dbl, 48, NPOS, 48, 256, 0,
                                     nullptr, nullptr, nullptr);
        // dt proj + softplus + exp(-dt): (8192 x 256), K=16
        k_gemm<<<dim3(2, 64), 256>>>((const float*)p_dbl, 48,
                                     dt_w + (size_t)i * 256 * 16, 16,
                                     (float*)p_dt, 256, NPOS, 256, 16, 2,
                                     dt_b + i * 256, (float*)p_r, nullptr);
        k_scanA<<<dim3(NCH, 2, BB), 128>>>();
        k_scanB<<<32, 256>>>();
        k_scanC<<<dim3(NCH, 2, BB), 128>>>(D_skip + i * 256);
        k_gate<<<NPOS, 256>>>(on_g + i * 256, on_b + i * 256, ori);
        // out-proj + residual into t
        k_gemm<<<dim3(2, 64), 256>>>((const float*)p_y2, 256,
                                     out_w + (size_t)i * 256 * 256, 256,
                                     (float*)p_t, 256, NPOS, 256, 256, 3,
                                     nullptr, nullptr, (const float*)p_t);
    }

    k_postln<<<NPOS, 256>>>(post_g, post_b);
    k_final_tr<<<dim3(8, 8, 32), dim3(32, 32)>>>(out);
}

// round 3
// speedup vs baseline: 1.2103x; 1.2103x over previous
#include <cuda_runtime.h>
#include <cuda_bf16.h>
#include <math.h>
#include <stdint.h>

#define BB   2
#define CC   256
#define LL   4096
#define DSZ  16
#define NCH  64
#define CLN  64          // LL / NCH
#define NPOS (BB*LL)     // 8192

// ---------------- scratch (static device globals; no allocation) ----------------
__device__ float g_t[NPOS*CC];          // running activation (B,L,C)
__device__ float g_xz[NPOS*2*CC];       // in-proj output (B,L,512)
__device__ float g_seq[NPOS*CC];        // conv+silu+flip output (B,L,C)
__device__ float g_dbl[NPOS*48];        // xproj output
__device__ float g_dt[NPOS*CC];         // softplus(dt)
__device__ float g_r[NPOS*CC];          // exp(-dt)
__device__ float g_y[NPOS*CC];          // scan output
__device__ float g_y2[NPOS*CC];         // postln tmp
__device__ float g_A[CC*DSZ];
__device__ int   g_fast;
__device__ float g_P[BB*CC*NCH*DSZ];
__device__ float g_hend[BB*CC*NCH*DSZ];
__device__ float g_hst[BB*CC*NCH*DSZ];
// bf16 split operand buffers (A = activations, W = weights)
__device__ __nv_bfloat16 g_ahi[NPOS*CC];
__device__ __nv_bfloat16 g_alo[NPOS*CC];
__device__ __nv_bfloat16 g_whi[512*CC];
__device__ __nv_bfloat16 g_wlo[512*CC];

// ---------------- helpers ----------------
__device__ __forceinline__ void blockMeanRstd256(float v, float& m, float& rs) {
    float s = v, s2 = v * v;
    #pragma unroll
    for (int o = 16; o; o >>= 1) {
        s  += __shfl_xor_sync(0xffffffffu, s,  o);
        s2 += __shfl_xor_sync(0xffffffffu, s2, o);
    }
    __shared__ float sm[8], sm2[8];
    int w = threadIdx.x >> 5, lane = threadIdx.x & 31;
    if (lane == 0) { sm[w] = s; sm2[w] = s2; }
    __syncthreads();
    if (w == 0) {
        float a = (lane < 8) ? sm[lane]  : 0.f;
        float b = (lane < 8) ? sm2[lane] : 0.f;
        #pragma unroll
        for (int o = 4; o; o >>= 1) {
            a += __shfl_xor_sync(0xffffffffu, a, o);
            b += __shfl_xor_sync(0xffffffffu, b, o);
        }
        if (lane == 0) { sm[0] = a; sm2[0] = b; }
    }
    __syncthreads();
    m  = sm[0] * (1.f / CC);
    rs = rsqrtf(sm2[0] * (1.f / CC) - m * m + 1e-5f);
}
__device__ __forceinline__ void split_store(float v, __nv_bfloat16* hi, __nv_bfloat16* lo, size_t i) {
    __nv_bfloat16 h = __float2bfloat16(v);
    hi[i] = h;
    lo[i] = __float2bfloat16(v - __bfloat162float(h));
}
__device__ __forceinline__ void mma16816(float c[4], const uint32_t a[4],
                                         uint32_t b0, uint32_t b1) {
    asm volatile(
        "mma.sync.aligned.m16n8k16.row.col.f32.bf16.bf16.f32 "
        "{%0,%1,%2,%3}, {%4,%5,%6,%7}, {%8,%9}, {%0,%1,%2,%3};"
        : "+f"(c[0]), "+f"(c[1]), "+f"(c[2]), "+f"(c[3])
        : "r"(a[0]), "r"(a[1]), "r"(a[2]), "r"(a[3]), "r"(b0), "r"(b1));
}

// ---------------- initial transpose: x(B,C,D,H,W) -> t(B, (h,w,d), C) ----------------
__global__ void k_init_tr(const float* __restrict__ x) {
    __shared__ float tile[32][33];
    int b = blockIdx.z >> 4, d = blockIdx.z & 15;
    int hw0 = blockIdx.x * 32, c0 = blockIdx.y * 32;
    int tx = threadIdx.x, ty = threadIdx.y;
    tile[ty][tx] = x[((size_t)(b*CC + c0 + ty) * 16 + d) * 256 + hw0 + tx];
    __syncthreads();
    g_t[((size_t)b*LL + (size_t)(hw0 + ty) * 16 + d) * CC + c0 + tx] = tile[tx][ty];
}

// ---------------- LN1 + bf16 split (feeds in-proj GEMM A) ----------------
__global__ void k_ln1(const float* __restrict__ g, const float* __restrict__ bvec) {
    int p = blockIdx.x, c = threadIdx.x;
    float v = g_t[(size_t)p * CC + c];
    float m, rs;
    blockMeanRstd256(v, m, rs);
    float o = (v - m) * rs * g[c] + bvec[c];
    split_store(o, g_ahi, g_alo, (size_t)p * CC + c);
}

// ---------------- weight split (with zero pad) ----------------
__global__ void k_wsplit(const float* __restrict__ src, int n, int ntot) {
    int i = blockIdx.x * 256 + threadIdx.x;
    if (i >= ntot) return;
    float v = (i < n) ? src[i] : 0.f;
    split_store(v, g_whi, g_wlo, i);
}

// ---------------- per-layer prep: A matrix, detect A_n == -(n+1) ----------------
__global__ void k_prep_A(const float* __restrict__ alog) {
    int c = threadIdx.x;
    __shared__ int ok;
    if (c == 0) ok = 1;
    __syncthreads();
    bool good = true;
    #pragma unroll
    for (int n = 0; n < DSZ; n++) {
        float a = -expf(alog[c * DSZ + n]);
        g_A[c * DSZ + n] = a;
        if (fabsf(a + (float)(n + 1)) > 1e-3f) good = false;
    }
    if (!good) atomicAnd(&ok, 0);
    __syncthreads();
    if (c == 0) g_fast = ok;
}

// ---------------- mma.sync bf16x3 GEMM: C[M,N] = A[M,256] * B[N,256]^T (fp32-accurate) ----------------
// mode 0: C = acc      mode 1: C += acc (residual)
// Block: 256 thr / 8 warps, tile 128 x NT, K-chunk 64, warp tile 32 x (NT/2).
// Smem rows padded to 40 u32 -> conflict-free fragment LDS.
template<int NT>
__global__ __launch_bounds__(256)
void k_mgemm(const uint32_t* __restrict__ Ahi, const uint32_t* __restrict__ Alo,
             const uint32_t* __restrict__ Bhi, const uint32_t* __restrict__ Blo,
             float* __restrict__ C, int ldc, int Nact, int mode) {
    constexpr int SR = 40;                  // u32 row stride (32 data + 8 pad)
    constexpr int NTILES = NT / 16;         // n-tiles (8 cols) per warp
    extern __shared__ uint32_t dsm[];
    uint32_t* sAh = dsm;
    uint32_t* sAl = dsm + 128 * SR;
    uint32_t* sBh = dsm + 2 * 128 * SR;
    uint32_t* sBl = dsm + 2 * 128 * SR + NT * SR;

    int tid = threadIdx.x, wid = tid >> 5, lane = tid & 31;
    int g2 = lane >> 2, t4 = lane & 3;
    int row0 = blockIdx.y * 128, col0 = blockIdx.x * NT;
    int m0 = (wid >> 1) * 32, n0 = (wid & 1) * (NT / 2);

    float acc[2][NTILES][4];
    #pragma unroll
    for (int mt = 0; mt < 2; mt++)
        #pragma unroll
        for (int nt = 0; nt < NTILES; nt++)
            #pragma unroll
            for (int j = 0; j < 4; j++) acc[mt][nt][j] = 0.f;

    for (int kc = 0; kc < 4; kc++) {        // K chunks of 64 bf16 (32 u32)
        int kw = kc * 32;
        // fill A tiles (128 rows x 8 uint4)
        #pragma unroll
        for (int i = 0; i < 4; i++) {
            int w = i * 256 + tid;
            int r = w >> 3, c4 = (w & 7) * 4;
            size_t gi = (size_t)(row0 + r) * 128 + kw + c4;
            *(uint4*)(sAh + r * SR + c4) = *(const uint4*)(Ahi + gi);
            *(uint4*)(sAl + r * SR + c4) = *(const uint4*)(Alo + gi);
        }
        // fill B tiles (NT rows x 8 uint4)
        #pragma unroll
        for (int i = 0; i < NT / 32; i++) {
            int w = i * 256 + tid;
            int r = w >> 3, c4 = (w & 7) * 4;
            size_t gi = (size_t)(col0 + r) * 128 + kw + c4;
            *(uint4*)(sBh + r * SR + c4) = *(const uint4*)(Bhi + gi);
            *(uint4*)(sBl + r * SR + c4) = *(const uint4*)(Blo + gi);
        }
        __syncthreads();
        #pragma unroll
        for (int ks = 0; ks < 4; ks++) {    // k16 steps inside chunk
            int k0 = ks * 8;
            uint32_t ah[2][4], al[2][4];
            #pragma unroll
            for (int mt = 0; mt < 2; mt++) {
                int ra = (m0 + mt * 16 + g2) * SR + k0 + t4;
                int rb = ra + 8 * SR;
                ah[mt][0] = sAh[ra];     ah[mt][1] = sAh[rb];
                ah[mt][2] = sAh[ra + 4]; ah[mt][3] = sAh[rb + 4];
                al[mt][0] = sAl[ra];     al[mt][1] = sAl[rb];
                al[mt][2] = sAl[ra + 4]; al[mt][3] = sAl[rb + 4];
            }
            #pragma unroll
            for (int nt = 0; nt < NTILES; nt++) {
                int rb0 = (n0 + nt * 8 + g2) * SR + k0 + t4;
                uint32_t bh0 = sBh[rb0], bh1 = sBh[rb0 + 4];
                uint32_t bl0 = sBl[rb0], bl1 = sBl[rb0 + 4];
                #pragma unroll
                for (int mt = 0; mt < 2; mt++) {
                    mma16816(acc[mt][nt], ah[mt], bh0, bh1);
                    mma16816(acc[mt][nt], ah[mt], bl0, bl1);
                    mma16816(acc[mt][nt], al[mt], bh0, bh1);
                }
            }
        }
        __syncthreads();
    }

    // epilogue
    #pragma unroll
    for (int mt = 0; mt < 2; mt++) {
        int rA = row0 + m0 + mt * 16 + g2;
        int rB = rA + 8;
        #pragma unroll
        for (int nt = 0; nt < NTILES; nt++) {
            int cA = col0 + n0 + nt * 8 + 2 * t4;
            #pragma unroll
            for (int j = 0; j < 2; j++) {
                int c = cA + j;
                if (c < Nact) {
                    float v0 = acc[mt][nt][j];
                    float v1 = acc[mt][nt][2 + j];
                    if (mode == 1) {
                        v0 += C[(size_t)rA * ldc + c];
                        v1 += C[(size_t)rB * ldc + c];
                    }
                    C[(size_t)rA * ldc + c] = v0;
                    C[(size_t)rB * ldc + c] = v1;
                }
            }
        }
    }
}

// ---------------- depthwise 3x3x3 conv + bias + SiLU + flip -> seq (fp32 + bf16 split) ----------------
__global__ void k_conv(const float* __restrict__ convw,
                       const float* __restrict__ convb, int ori) {
    int bidx = blockIdx.x;
    int b = bidx >> 8, h = (bidx >> 4) & 15, w = bidx & 15;
    int c = threadIdx.x;
    __shared__ float ws[256 * 27];
    for (int i = threadIdx.x; i < 256 * 27; i += 256) ws[i] = convw[i];
    __syncthreads();
    float wr[27];
    #pragma unroll
    for (int j = 0; j < 27; j++) wr[j] = ws[c * 27 + j];
    float bias = convb[c];
    int fh = (ori & 1) ? 15 - h : h;
    int fw = (ori & 2) ? 15 - w : w;
    for (int d = 0; d < 16; d++) {
        float acc = bias;
        #pragma unroll
        for (int s1 = 0; s1 < 3; s1++) {
            int hh = h + s1 - 1; if (hh < 0 || hh > 15) continue;
            #pragma unroll
            for (int s2 = 0; s2 < 3; s2++) {
                int ww = w + s2 - 1; if (ww < 0 || ww > 15) continue;
                #pragma unroll
                for (int s3 = 0; s3 < 3; s3++) {
                    int dd = d + s3 - 1; if (dd < 0 || dd > 15) continue;
                    int p = b * LL + (hh * 16 + ww) * 16 + dd;
                    acc += wr[s1 * 9 + s2 * 3 + s3] * g_xz[(size_t)p * 512 + c];
                }
            }
        }
        float sv = acc / (1.f + expf(-acc));
        int fd = (ori & 4) ? 15 - d : d;
        int dl = (fh * 16 + fw) * 16 + fd;
        size_t oi = ((size_t)b * LL + dl) * CC + c;
        g_seq[oi] = sv;
        split_store(sv, g_ahi, g_alo, oi);
    }
}

// ---------------- dt-proj (K=16) + softplus + exp(-dt), SIMT ----------------
__global__ void k_dtexp(const float* __restrict__ dtw, const float* __restrict__ dtb) {
    int p = blockIdx.x, c = threadIdx.x;
    __shared__ float d[16];
    if (c < 16) d[c] = g_dbl[(size_t)p * 48 + c];
    __syncthreads();
    float acc = dtb[c];
    #pragma unroll
    for (int j = 0; j < 16; j++) acc += d[j] * dtw[c * 16 + j];
    float sp = fmaxf(acc, 0.f) + log1pf(expf(-fabsf(acc)));
    g_dt[(size_t)p * CC + c] = sp;
    g_r[(size_t)p * CC + c]  = expf(-sp);
}

// ---------------- chunked selective scan: phase A ----------------
__global__ void k_scanA() {
    int c = blockIdx.y * 128 + threadIdx.x;
    int ch = blockIdx.x, b = blockIdx.z;
    __shared__ float Bsm[CLN][DSZ];
    for (int i = threadIdx.x; i < CLN * DSZ; i += 128) {
        int t = i >> 4, n = i & 15;
        Bsm[t][n] = g_dbl[((size_t)b * LL + ch * CLN + t) * 48 + 16 + n];
    }
    __syncthreads();
    float h[DSZ], P[DSZ];
    #pragma unroll
    for (int n = 0; n < DSZ; n++) { h[n] = 0.f; P[n] = 1.f; }
    size_t base = ((size_t)b * LL + ch * CLN) * CC + c;
    if (g_fast) {
        for (int t = 0; t < CLN; t++) {
            float rv = g_r[base], dtv = g_dt[base], xv = g_seq[base];
            base += CC;
            float dtx = dtv * xv;
            float rp = rv;
            #pragma unroll
            for (int n = 0; n < DSZ; n++) {
                h[n] = rp * h[n] + dtx * Bsm[t][n];
                P[n] *= rp;
                rp *= rv;
            }
        }
    } else {
        for (int t = 0; t < CLN; t++) {
            float dtv = g_dt[base], xv = g_seq[base];
            base += CC;
            float dtx = dtv * xv;
            #pragma unroll
            for (int n = 0; n < DSZ; n++) {
                float dA = __expf(dtv * g_A[c * DSZ + n]);
                h[n] = dA * h[n] + dtx * Bsm[t][n];
                P[n] *= dA;
            }
        }
    }
    size_t off = (((size_t)(b * CC + c)) * NCH + ch) * DSZ;
    #pragma unroll
    for (int n = 0; n < DSZ; n++) { g_hend[off + n] = h[n]; g_P[off + n] = P[n]; }
}

// ---------------- phase B: sequential chunk combine ----------------
__global__ void k_scanB() {
    int idx = blockIdx.x * 256 + threadIdx.x;
    if (idx >= BB * CC * DSZ) return;
    int n = idx & 15, bc = idx >> 4;
    float H = 0.f;
    size_t base = (size_t)bc * NCH * DSZ + n;
    for (int k = 0; k < NCH; k++) {
        g_hst[base + (size_t)k * DSZ] = H;
        H = g_P[base + (size_t)k * DSZ] * H + g_hend[base + (size_t)k * DSZ];
    }
}

// ---------------- phase C: replay, produce y ----------------
__global__ void k_scanC(const float* __restrict__ Dv) {
    int c = blockIdx.y * 128 + threadIdx.x;
    int ch = blockIdx.x, b = blockIdx.z;
    __shared__ float Bsm[CLN][DSZ];
    __shared__ float Csm[CLN][DSZ];
    for (int i = threadIdx.x; i < CLN * DSZ; i += 128) {
        int t = i >> 4, n = i & 15;
        size_t rb = ((size_t)b * LL + ch * CLN + t) * 48;
        Bsm[t][n] = g_dbl[rb + 16 + n];
        Csm[t][n] = g_dbl[rb + 32 + n];
    }
    __syncthreads();
    float h[DSZ];
    size_t off = (((size_t)(b * CC + c)) * NCH + ch) * DSZ;
    #pragma unroll
    for (int n = 0; n < DSZ; n++) h[n] = g_hst[off + n];
    float Dc = Dv[c];
    size_t base = ((size_t)b * LL + ch * CLN) * CC + c;
    if (g_fast) {
        for (int t = 0; t < CLN; t++) {
            float rv = g_r[base], dtv = g_dt[base], xv = g_seq[base];
            float dtx = dtv * xv;
            float y = 0.f;
            float rp = rv;
            #pragma unroll
            for (int n = 0; n < DSZ; n++) {
                h[n] = rp * h[n] + dtx * Bsm[t][n];
                y += h[n] * Csm[t][n];
                rp *= rv;
            }
            g_y[base] = y + Dc * xv;
            base += CC;
        }
    } else {
        for (int t = 0; t < CLN; t++) {
            float dtv = g_dt[base], xv = g_seq[base];
            float dtx = dtv * xv;
            float y = 0.f;
            #pragma unroll
            for (int n = 0; n < DSZ; n++) {
                float dA = __expf(dtv * g_A[c * DSZ + n]);
                h[n] = dA * h[n] + dtx * Bsm[t][n];
                y += h[n] * Csm[t][n];
            }
            g_y[base] = y + Dc * xv;
            base += CC;
        }
    }
}

// ---------------- unflip + output LN + SiLU gate -> bf16 split (out-proj A) ----------------
__global__ void k_gate(const float* __restrict__ og,
                       const float* __restrict__ ob, int ori) {
    int p = blockIdx.x, c = threadIdx.x;
    int b = p >> 12, l = p & 4095;
    int h = l >> 8, w = (l >> 4) & 15, d = l & 15;
    if (ori & 1) h = 15 - h;
    if (ori & 2) w = 15 - w;
    if (ori & 4) d = 15 - d;
    int ls = (h << 8) | (w << 4) | d;
    float v = g_y[((size_t)((b << 12) | ls)) * CC + c];
    float m, rs;
    blockMeanRstd256(v, m, rs);
    float z = g_xz[(size_t)p * 512 + 256 + c];
    float sz = z / (1.f + expf(-z));
    float o = ((v - m) * rs * og[c] + ob[c]) * sz;
    split_store(o, g_ahi, g_alo, (size_t)p * CC + c);
}

// ---------------- final post-LN ----------------
__global__ void k_postln(const float* __restrict__ g, const float* __restrict__ bvec) {
    int p = blockIdx.x, c = threadIdx.x;
    float v = g_t[(size_t)p * CC + c];
    float m, rs;
    blockMeanRstd256(v, m, rs);
    g_y2[(size_t)p * CC + c] = (v - m) * rs * g[c] + bvec[c];
}

// ---------------- final transpose ----------------
__global__ void k_final_tr(float* __restrict__ out) {
    __shared__ float tile[32][33];
    int b = blockIdx.z >> 4, d = blockIdx.z & 15;
    int hw0 = blockIdx.x * 32, c0 = blockIdx.y * 32;
    int tx = threadIdx.x, ty = threadIdx.y;
    tile[ty][tx] = g_y2[((size_t)b * LL + (size_t)(hw0 + ty) * 16 + d) * CC + c0 + tx];
    __syncthreads();
    out[((size_t)(b * CC + c0 + ty) * 16 + d) * 256 + hw0 + tx] = tile[tx][ty];
}

// ---------------- host ----------------
extern "C" void kernel_launch(void* const* d_in, const int* in_sizes, int n_in,
                              void* d_out, int out_size) {
    const float* x       = (const float*)d_in[0];
    const float* in_w    = (const float*)d_in[1];
    const float* conv_w  = (const float*)d_in[2];
    const float* conv_b  = (const float*)d_in[3];
    const float* xproj_w = (const float*)d_in[4];
    const float* dt_w    = (const float*)d_in[5];
    const float* dt_b    = (const float*)d_in[6];
    const float* A_log   = (const float*)d_in[7];
    const float* D_skip  = (const float*)d_in[8];
    const float* on_g    = (const float*)d_in[9];
    const float* on_b    = (const float*)d_in[10];
    const float* out_w   = (const float*)d_in[11];
    const float* ln1_g   = (const float*)d_in[12];
    const float* ln1_b   = (const float*)d_in[13];
    const float* post_g  = (const float*)d_in[14];
    const float* post_b  = (const float*)d_in[15];
    float* out = (float*)d_out;

    void *p_t, *p_xz, *p_dbl, *p_ahi, *p_alo, *p_whi, *p_wlo;
    cudaGetSymbolAddress(&p_t,   g_t);
    cudaGetSymbolAddress(&p_xz,  g_xz);
    cudaGetSymbolAddress(&p_dbl, g_dbl);
    cudaGetSymbolAddress(&p_ahi, g_ahi);
    cudaGetSymbolAddress(&p_alo, g_alo);
    cudaGetSymbolAddress(&p_whi, g_whi);
    cudaGetSymbolAddress(&p_wlo, g_wlo);

    const int SM128 = (2 * 128 * 40 + 2 * 128 * 40) * 4;   // 81920 B
    const int SM64  = (2 * 128 * 40 + 2 * 64 * 40) * 4;    // 61440 B
    static int attr_done = 0;
    if (!attr_done) {
        cudaFuncSetAttribute(k_mgemm<128>, cudaFuncAttributeMaxDynamicSharedMemorySize, SM128);
        cudaFuncSetAttribute(k_mgemm<64>,  cudaFuncAttributeMaxDynamicSharedMemorySize, SM64);
        attr_done = 1;
    }

    k_init_tr<<<dim3(8, 8, 32), dim3(32, 32)>>>(x);

    for (int i = 0; i < 4; i++) {
        int ori = i;  // i % 8
        k_prep_A<<<1, 256>>>(A_log + (size_t)i * 256 * 16);
        k_ln1<<<NPOS, 256>>>(ln1_g + i * 256, ln1_b + i * 256);
        k_wsplit<<<512, 256>>>(in_w + (size_t)i * 512 * 256, 512 * 256, 512 * 256);
        // in-proj: (8192 x 512) = LN(t) * in_w^T
        k_mgemm<128><<<dim3(4, 64), 256, SM128>>>(
            (const uint32_t*)p_ahi, (const uint32_t*)p_alo,
            (const uint32_t*)p_whi, (const uint32_t*)p_wlo,
            (float*)p_xz, 512, 512, 0);
        k_conv<<<BB * 256, 256>>>(conv_w + (size_t)i * 256 * 27, conv_b + i * 256, ori);
        // xproj: (8192 x 48), weights padded to 64 rows
        k_wsplit<<<64, 256>>>(xproj_w + (size_t)i * 48 * 256, 48 * 256, 64 * 256);
        k_mgemm<64><<<dim3(1, 64), 256, SM64>>>(
            (const uint32_t*)p_ahi, (const uint32_t*)p_alo,
            (const uint32_t*)p_whi, (const uint32_t*)p_wlo,
            (float*)p_dbl, 48, 48, 0);
        k_dtexp<<<NPOS, 256>>>(dt_w + (size_t)i * 256 * 16, dt_b + i * 256);
        k_scanA<<<dim3(NCH, 2, BB), 128>>>();
        k_scanB<<<32, 256>>>();
        k_scanC<<<dim3(NCH, 2, BB), 128>>>(D_skip + i * 256);
        k_gate<<<NPOS, 256>>>(on_g + i * 256, on_b + i * 256, ori);
        // out-proj + residual into t
        k_wsplit<<<256, 256>>>(out_w + (size_t)i * 256 * 256, 256 * 256, 256 * 256);
        k_mgemm<128><<<dim3(2, 64), 256, SM128>>>(
            (const uint32_t*)p_ahi, (const uint32_t*)p_alo,
            (const uint32_t*)p_whi, (const uint32_t*)p_wlo,
            (float*)p_t, 256, 256, 1);
    }

    k_postln<<<NPOS, 256>>>(post_g, post_b);
    k_final_tr<<<dim3(8, 8, 32), dim3(32, 32)>>>(out);
}

// round 4
// speedup vs baseline: 2.0844x; 1.7222x over previous
#include <cuda_runtime.h>
#include <cuda_bf16.h>
#include <math.h>
#include <stdint.h>

#define BB   2
#define CC   256
#define LL   4096
#define DSZ  16
#define NCH  64
#define CLN  64          // LL / NCH
#define NPOS (BB*LL)     // 8192

// weight-split buffer layout (bf16 elements)
#define WOFF_IN(i)   ((i) * 131072)               // 4 x 512x256
#define WOFF_XP(i)   (524288 + (i) * 16384)       // 4 x 64x256 (48 padded to 64)
#define WOFF_OUT(i)  (589824 + (i) * 65536)       // 4 x 256x256
#define WTOT 851968

// ---------------- scratch (static device globals; no allocation) ----------------
__device__ float g_t[NPOS*CC];          // running activation (B,L,C)
__device__ float g_xz[NPOS*2*CC];       // in-proj output (B,L,512)
__device__ float g_seq[NPOS*CC];        // conv+silu+flip output (B,L,C)
__device__ float g_dbl[NPOS*48];        // xproj output
__device__ float g_y[NPOS*CC];          // scan output
__device__ float g_rowm[NPOS];
__device__ float g_rowrs[NPOS];
__device__ float g_A[4*CC*DSZ];
__device__ int   g_fastA[4];
__device__ float g_P[BB*CC*NCH*DSZ];
__device__ float g_hend[BB*CC*NCH*DSZ];
__device__ float g_hst[BB*CC*NCH*DSZ];
__device__ __nv_bfloat16 g_ahi[NPOS*CC];
__device__ __nv_bfloat16 g_alo[NPOS*CC];
__device__ __nv_bfloat16 g_whi[WTOT];
__device__ __nv_bfloat16 g_wlo[WTOT];

// ---------------- helpers ----------------
__device__ __forceinline__ void warpRed2(float& s, float& s2) {
    #pragma unroll
    for (int o = 16; o; o >>= 1) {
        s  += __shfl_xor_sync(0xffffffffu, s,  o);
        s2 += __shfl_xor_sync(0xffffffffu, s2, o);
    }
}
__device__ __forceinline__ uint32_t packbf2(float a, float b) {
    __nv_bfloat162 t = __floats2bfloat162_rn(a, b);   // {x=a, y=b}; x in low half
    return *(uint32_t*)&t;
}
__device__ __forceinline__ void split8_store(const float o[8],
                                             __nv_bfloat16* hiB, __nv_bfloat16* loB,
                                             size_t rowoff, int lane) {
    float hf[8], lf[8];
    #pragma unroll
    for (int k = 0; k < 8; k++) {
        __nv_bfloat16 h = __float2bfloat16(o[k]);
        hf[k] = __bfloat162float(h);
        lf[k] = o[k] - hf[k];
    }
    uint4 uh, ul;
    uh.x = packbf2(hf[0], hf[1]); uh.y = packbf2(hf[2], hf[3]);
    uh.z = packbf2(hf[4], hf[5]); uh.w = packbf2(hf[6], hf[7]);
    ul.x = packbf2(lf[0], lf[1]); ul.y = packbf2(lf[2], lf[3]);
    ul.z = packbf2(lf[4], lf[5]); ul.w = packbf2(lf[6], lf[7]);
    ((uint4*)(hiB + rowoff))[lane] = uh;
    ((uint4*)(loB + rowoff))[lane] = ul;
}
__device__ __forceinline__ void split_store(float v, __nv_bfloat16* hi, __nv_bfloat16* lo, size_t i) {
    __nv_bfloat16 h = __float2bfloat16(v);
    hi[i] = h;
    lo[i] = __float2bfloat16(v - __bfloat162float(h));
}
__device__ __forceinline__ void mma16816(float c[4], const uint32_t a[4],
                                         uint32_t b0, uint32_t b1) {
    asm volatile(
        "mma.sync.aligned.m16n8k16.row.col.f32.bf16.bf16.f32 "
        "{%0,%1,%2,%3}, {%4,%5,%6,%7}, {%8,%9}, {%0,%1,%2,%3};"
        : "+f"(c[0]), "+f"(c[1]), "+f"(c[2]), "+f"(c[3])
        : "r"(a[0]), "r"(a[1]), "r"(a[2]), "r"(a[3]), "r"(b0), "r"(b1));
}

// ---------------- all-layer weight split (1 launch) ----------------
__global__ void k_wsplit_all(const float* __restrict__ inw,
                             const float* __restrict__ xpw,
                             const float* __restrict__ ow) {
    int idx = blockIdx.x * 256 + threadIdx.x;
    if (idx >= WTOT) return;
    float v;
    if (idx < 524288) {
        v = inw[idx];
    } else if (idx < 589824) {
        int rel = idx - 524288;
        int layer = rel >> 14, w = rel & 16383;
        int row = w >> 8, col = w & 255;
        v = (row < 48) ? xpw[layer * 12288 + row * 256 + col] : 0.f;
    } else {
        v = ow[idx - 589824];
    }
    split_store(v, g_whi, g_wlo, idx);
}

// ---------------- all-layer A prep (1 launch) ----------------
__global__ void k_prepA_all(const float* __restrict__ alog) {
    int layer = blockIdx.x, c = threadIdx.x;
    __shared__ int ok;
    if (c == 0) ok = 1;
    __syncthreads();
    bool good = true;
    #pragma unroll
    for (int n = 0; n < DSZ; n++) {
        float a = -expf(alog[(layer * 256 + c) * DSZ + n]);
        g_A[(layer * 256 + c) * DSZ + n] = a;
        if (fabsf(a + (float)(n + 1)) > 1e-3f) good = false;
    }
    if (!good) atomicAnd(&ok, 0);
    __syncthreads();
    if (c == 0) g_fastA[layer] = ok;
}

// ---------------- initial transpose: x(B,C,D,H,W) -> t(B, (h,w,d), C) ----------------
__global__ void k_init_tr(const float* __restrict__ x) {
    __shared__ float tile[32][33];
    int b = blockIdx.z >> 4, d = blockIdx.z & 15;
    int hw0 = blockIdx.x * 32, c0 = blockIdx.y * 32;
    int tx = threadIdx.x, ty = threadIdx.y;
    tile[ty][tx] = x[((size_t)(b*CC + c0 + ty) * 16 + d) * 256 + hw0 + tx];
    __syncthreads();
    g_t[((size_t)b*LL + (size_t)(hw0 + ty) * 16 + d) * CC + c0 + tx] = tile[tx][ty];
}

// ---------------- LN1 (warp per row) + bf16 split ----------------
__global__ __launch_bounds__(256)
void k_ln1(const float* __restrict__ g, const float* __restrict__ bvec) {
    int warp = threadIdx.x >> 5, lane = threadIdx.x & 31;
    int p = blockIdx.x * 8 + warp;
    const float4* row = (const float4*)(g_t + (size_t)p * CC);
    float4 v0 = row[lane * 2], v1 = row[lane * 2 + 1];
    float s  = v0.x + v0.y + v0.z + v0.w + v1.x + v1.y + v1.z + v1.w;
    float s2 = v0.x*v0.x + v0.y*v0.y + v0.z*v0.z + v0.w*v0.w
             + v1.x*v1.x + v1.y*v1.y + v1.z*v1.z + v1.w*v1.w;
    warpRed2(s, s2);
    float m  = s * (1.f / CC);
    float rs = rsqrtf(s2 * (1.f / CC) - m * m + 1e-5f);
    float4 gg0 = ((const float4*)g)[lane * 2],    gg1 = ((const float4*)g)[lane * 2 + 1];
    float4 bb0 = ((const float4*)bvec)[lane * 2], bb1 = ((const float4*)bvec)[lane * 2 + 1];
    float o[8];
    o[0] = (v0.x - m) * rs * gg0.x + bb0.x;  o[1] = (v0.y - m) * rs * gg0.y + bb0.y;
    o[2] = (v0.z - m) * rs * gg0.z + bb0.z;  o[3] = (v0.w - m) * rs * gg0.w + bb0.w;
    o[4] = (v1.x - m) * rs * gg1.x + bb1.x;  o[5] = (v1.y - m) * rs * gg1.y + bb1.y;
    o[6] = (v1.z - m) * rs * gg1.z + bb1.z;  o[7] = (v1.w - m) * rs * gg1.w + bb1.w;
    split8_store(o, g_ahi, g_alo, (size_t)p * CC, lane);
}

// ---------------- mma.sync bf16x3 GEMM (unchanged from R3, B via offset ptrs) ----------------
template<int NT>
__global__ __launch_bounds__(256)
void k_mgemm(const uint32_t* __restrict__ Ahi, const uint32_t* __restrict__ Alo,
             const uint32_t* __restrict__ Bhi, const uint32_t* __restrict__ Blo,
             float* __restrict__ C, int ldc, int Nact, int mode) {
    constexpr int SR = 40;
    constexpr int NTILES = NT / 16;
    extern __shared__ uint32_t dsm[];
    uint32_t* sAh = dsm;
    uint32_t* sAl = dsm + 128 * SR;
    uint32_t* sBh = dsm + 2 * 128 * SR;
    uint32_t* sBl = dsm + 2 * 128 * SR + NT * SR;

    int tid = threadIdx.x, wid = tid >> 5, lane = tid & 31;
    int g2 = lane >> 2, t4 = lane & 3;
    int row0 = blockIdx.y * 128, col0 = blockIdx.x * NT;
    int m0 = (wid >> 1) * 32, n0 = (wid & 1) * (NT / 2);

    float acc[2][NTILES][4];
    #pragma unroll
    for (int mt = 0; mt < 2; mt++)
        #pragma unroll
        for (int nt = 0; nt < NTILES; nt++)
            #pragma unroll
            for (int j = 0; j < 4; j++) acc[mt][nt][j] = 0.f;

    for (int kc = 0; kc < 4; kc++) {
        int kw = kc * 32;
        #pragma unroll
        for (int i = 0; i < 4; i++) {
            int w = i * 256 + tid;
            int r = w >> 3, c4 = (w & 7) * 4;
            size_t gi = (size_t)(row0 + r) * 128 + kw + c4;
            *(uint4*)(sAh + r * SR + c4) = *(const uint4*)(Ahi + gi);
            *(uint4*)(sAl + r * SR + c4) = *(const uint4*)(Alo + gi);
        }
        #pragma unroll
        for (int i = 0; i < NT / 32; i++) {
            int w = i * 256 + tid;
            int r = w >> 3, c4 = (w & 7) * 4;
            size_t gi = (size_t)(col0 + r) * 128 + kw + c4;
            *(uint4*)(sBh + r * SR + c4) = *(const uint4*)(Bhi + gi);
            *(uint4*)(sBl + r * SR + c4) = *(const uint4*)(Blo + gi);
        }
        __syncthreads();
        #pragma unroll
        for (int ks = 0; ks < 4; ks++) {
            int k0 = ks * 8;
            uint32_t ah[2][4], al[2][4];
            #pragma unroll
            for (int mt = 0; mt < 2; mt++) {
                int ra = (m0 + mt * 16 + g2) * SR + k0 + t4;
                int rb = ra + 8 * SR;
                ah[mt][0] = sAh[ra];     ah[mt][1] = sAh[rb];
                ah[mt][2] = sAh[ra + 4]; ah[mt][3] = sAh[rb + 4];
                al[mt][0] = sAl[ra];     al[mt][1] = sAl[rb];
                al[mt][2] = sAl[ra + 4]; al[mt][3] = sAl[rb + 4];
            }
            #pragma unroll
            for (int nt = 0; nt < NTILES; nt++) {
                int rb0 = (n0 + nt * 8 + g2) * SR + k0 + t4;
                uint32_t bh0 = sBh[rb0], bh1 = sBh[rb0 + 4];
                uint32_t bl0 = sBl[rb0], bl1 = sBl[rb0 + 4];
                #pragma unroll
                for (int mt = 0; mt < 2; mt++) {
                    mma16816(acc[mt][nt], ah[mt], bh0, bh1);
                    mma16816(acc[mt][nt], ah[mt], bl0, bl1);
                    mma16816(acc[mt][nt], al[mt], bh0, bh1);
                }
            }
        }
        __syncthreads();
    }

    #pragma unroll
    for (int mt = 0; mt < 2; mt++) {
        int rA = row0 + m0 + mt * 16 + g2;
        int rB = rA + 8;
        #pragma unroll
        for (int nt = 0; nt < NTILES; nt++) {
            int cA = col0 + n0 + nt * 8 + 2 * t4;
            #pragma unroll
            for (int j = 0; j < 2; j++) {
                int c = cA + j;
                if (c < Nact) {
                    float v0 = acc[mt][nt][j];
                    float v1 = acc[mt][nt][2 + j];
                    if (mode == 1) {
                        v0 += C[(size_t)rA * ldc + c];
                        v1 += C[(size_t)rB * ldc + c];
                    }
                    C[(size_t)rA * ldc + c] = v0;
                    C[(size_t)rB * ldc + c] = v1;
                }
            }
        }
    }
}

// ---------------- depthwise 3x3x3 conv + SiLU + flip, column-reuse ----------------
__global__ __launch_bounds__(256)
void k_conv(const float* __restrict__ convw,
            const float* __restrict__ convb, int ori) {
    int bidx = blockIdx.x;
    int b = bidx >> 8, h = (bidx >> 4) & 15, w = bidx & 15;
    int c = threadIdx.x;
    __shared__ float ws[256 * 27];
    for (int i = threadIdx.x; i < 256 * 27; i += 256) ws[i] = convw[i];
    __syncthreads();
    float wr[27];
    #pragma unroll
    for (int j = 0; j < 27; j++) wr[j] = ws[c * 27 + j];
    float bias = convb[c];
    float acc[16];
    #pragma unroll
    for (int d = 0; d < 16; d++) acc[d] = bias;

    #pragma unroll
    for (int s1 = 0; s1 < 3; s1++) {
        int hh = h + s1 - 1; if (hh < 0 || hh > 15) continue;
        #pragma unroll
        for (int s2 = 0; s2 < 3; s2++) {
            int ww = w + s2 - 1; if (ww < 0 || ww > 15) continue;
            size_t cb = ((size_t)(b * LL + (hh * 16 + ww) * 16)) * 512 + c;
            float col[16];
            #pragma unroll
            for (int dd = 0; dd < 16; dd++) col[dd] = g_xz[cb + (size_t)dd * 512];
            float w0 = wr[s1 * 9 + s2 * 3 + 0];
            float w1 = wr[s1 * 9 + s2 * 3 + 1];
            float w2 = wr[s1 * 9 + s2 * 3 + 2];
            #pragma unroll
            for (int d = 0; d < 16; d++) {
                float a = w1 * col[d];
                if (d > 0)  a += w0 * col[d - 1];
                if (d < 15) a += w2 * col[d + 1];
                acc[d] += a;
            }
        }
    }
    int fh = (ori & 1) ? 15 - h : h;
    int fw = (ori & 2) ? 15 - w : w;
    #pragma unroll
    for (int d = 0; d < 16; d++) {
        float sv = acc[d] / (1.f + expf(-acc[d]));
        int fd = (ori & 4) ? 15 - d : d;
        size_t oi = ((size_t)b * LL + (fh * 16 + fw) * 16 + fd) * CC + c;
        g_seq[oi] = sv;
        split_store(sv, g_ahi, g_alo, oi);
    }
}

// ---------------- scan phase A with fused dt-proj ----------------
__global__ __launch_bounds__(128)
void k_scanA(int layer, const float* __restrict__ dtw_, const float* __restrict__ dtb_) {
    int c = blockIdx.y * 128 + threadIdx.x;
    int ch = blockIdx.x, b = blockIdx.z;
    __shared__ float dtsm[CLN][DSZ];
    __shared__ float Bsm[CLN][DSZ];
    for (int i = threadIdx.x; i < CLN * 32; i += 128) {
        int t = i >> 5, j = i & 31;
        float v = g_dbl[((size_t)b * LL + ch * CLN + t) * 48 + j];
        if (j < 16) dtsm[t][j] = v; else Bsm[t][j - 16] = v;
    }
    __syncthreads();
    float dw[DSZ];
    #pragma unroll
    for (int j = 0; j < DSZ; j++) dw[j] = dtw_[c * DSZ + j];
    float db = dtb_[c];
    float h[DSZ], P[DSZ];
    #pragma unroll
    for (int n = 0; n < DSZ; n++) { h[n] = 0.f; P[n] = 1.f; }
    size_t base = ((size_t)b * LL + ch * CLN) * CC + c;
    if (g_fastA[layer]) {
        for (int t = 0; t < CLN; t++) {
            float xv = g_seq[base]; base += CC;
            float traw = db;
            #pragma unroll
            for (int j = 0; j < DSZ; j++) traw += dw[j] * dtsm[t][j];
            float sp = fmaxf(traw, 0.f) + log1pf(expf(-fabsf(traw)));
            float rv = expf(-sp);
            float dtx = sp * xv;
            float rp = rv;
            #pragma unroll
            for (int n = 0; n < DSZ; n++) {
                h[n] = rp * h[n] + dtx * Bsm[t][n];
                P[n] *= rp;
                rp *= rv;
            }
        }
    } else {
        for (int t = 0; t < CLN; t++) {
            float xv = g_seq[base]; base += CC;
            float traw = db;
            #pragma unroll
            for (int j = 0; j < DSZ; j++) traw += dw[j] * dtsm[t][j];
            float sp = fmaxf(traw, 0.f) + log1pf(expf(-fabsf(traw)));
            float dtx = sp * xv;
            #pragma unroll
            for (int n = 0; n < DSZ; n++) {
                float dA = __expf(sp * g_A[((layer * 256) + c) * DSZ + n]);
                h[n] = dA * h[n] + dtx * Bsm[t][n];
                P[n] *= dA;
            }
        }
    }
    size_t off = (((size_t)(b * CC + c)) * NCH + ch) * DSZ;
    #pragma unroll
    for (int n = 0; n < DSZ; n++) { g_hend[off + n] = h[n]; g_P[off + n] = P[n]; }
}

// ---------------- phase B: sequential chunk combine ----------------
__global__ void k_scanB() {
    int idx = blockIdx.x * 256 + threadIdx.x;
    if (idx >= BB * CC * DSZ) return;
    int n = idx & 15, bc = idx >> 4;
    float H = 0.f;
    size_t base = (size_t)bc * NCH * DSZ + n;
    for (int k = 0; k < NCH; k++) {
        g_hst[base + (size_t)k * DSZ] = H;
        H = g_P[base + (size_t)k * DSZ] * H + g_hend[base + (size_t)k * DSZ];
    }
}

// ---------------- scan phase C with fused dt-proj ----------------
__global__ __launch_bounds__(128)
void k_scanC(int layer, const float* __restrict__ dtw_, const float* __restrict__ dtb_,
             const float* __restrict__ Dv) {
    int c = blockIdx.y * 128 + threadIdx.x;
    int ch = blockIdx.x, b = blockIdx.z;
    __shared__ float dtsm[CLN][DSZ];
    __shared__ float Bsm[CLN][DSZ];
    __shared__ float Csm[CLN][DSZ];
    for (int i = threadIdx.x; i < CLN * 48; i += 128) {
        int t = i / 48, j = i % 48;
        float v = g_dbl[((size_t)b * LL + ch * CLN + t) * 48 + j];
        if (j < 16) dtsm[t][j] = v;
        else if (j < 32) Bsm[t][j - 16] = v;
        else Csm[t][j - 32] = v;
    }
    __syncthreads();
    float dw[DSZ];
    #pragma unroll
    for (int j = 0; j < DSZ; j++) dw[j] = dtw_[c * DSZ + j];
    float db = dtb_[c];
    float h[DSZ];
    size_t off = (((size_t)(b * CC + c)) * NCH + ch) * DSZ;
    #pragma unroll
    for (int n = 0; n < DSZ; n++) h[n] = g_hst[off + n];
    float Dc = Dv[c];
    size_t base = ((size_t)b * LL + ch * CLN) * CC + c;
    if (g_fastA[layer]) {
        for (int t = 0; t < CLN; t++) {
            float xv = g_seq[base];
            float traw = db;
            #pragma unroll
            for (int j = 0; j < DSZ; j++) traw += dw[j] * dtsm[t][j];
            float sp = fmaxf(traw, 0.f) + log1pf(expf(-fabsf(traw)));
            float rv = expf(-sp);
            float dtx = sp * xv;
            float y = 0.f;
            float rp = rv;
            #pragma unroll
            for (int n = 0; n < DSZ; n++) {
                h[n] = rp * h[n] + dtx * Bsm[t][n];
                y += h[n] * Csm[t][n];
                rp *= rv;
            }
            g_y[base] = y + Dc * xv;
            base += CC;
        }
    } else {
        for (int t = 0; t < CLN; t++) {
            float xv = g_seq[base];
            float traw = db;
            #pragma unroll
            for (int j = 0; j < DSZ; j++) traw += dw[j] * dtsm[t][j];
            float sp = fmaxf(traw, 0.f) + log1pf(expf(-fabsf(traw)));
            float dtx = sp * xv;
            float y = 0.f;
            #pragma unroll
            for (int n = 0; n < DSZ; n++) {
                float dA = __expf(sp * g_A[((layer * 256) + c) * DSZ + n]);
                h[n] = dA * h[n] + dtx * Bsm[t][n];
                y += h[n] * Csm[t][n];
            }
            g_y[base] = y + Dc * xv;
            base += CC;
        }
    }
}

// ---------------- unflip + output LN + SiLU gate (warp per row) ----------------
__global__ __launch_bounds__(256)
void k_gate(const float* __restrict__ og, const float* __restrict__ ob, int ori) {
    int warp = threadIdx.x >> 5, lane = threadIdx.x & 31;
    int p = blockIdx.x * 8 + warp;
    int b = p >> 12, l = p & 4095;
    int h = l >> 8, w = (l >> 4) & 15, d = l & 15;
    if (ori & 1) h = 15 - h;
    if (ori & 2) w = 15 - w;
    if (ori & 4) d = 15 - d;
    int ls = (h << 8) | (w << 4) | d;
    const float4* yr = (const float4*)(g_y + ((size_t)((b << 12) | ls)) * CC);
    float4 v0 = yr[lane * 2], v1 = yr[lane * 2 + 1];
    float s  = v0.x + v0.y + v0.z + v0.w + v1.x + v1.y + v1.z + v1.w;
    float s2 = v0.x*v0.x + v0.y*v0.y + v0.z*v0.z + v0.w*v0.w
             + v1.x*v1.x + v1.y*v1.y + v1.z*v1.z + v1.w*v1.w;
    warpRed2(s, s2);
    float m  = s * (1.f / CC);
    float rs = rsqrtf(s2 * (1.f / CC) - m * m + 1e-5f);
    const float4* zr = (const float4*)(g_xz + (size_t)p * 512 + 256);
    float4 z0 = zr[lane * 2], z1 = zr[lane * 2 + 1];
    float4 gg0 = ((const float4*)og)[lane * 2], gg1 = ((const float4*)og)[lane * 2 + 1];
    float4 bb0 = ((const float4*)ob)[lane * 2], bb1 = ((const float4*)ob)[lane * 2 + 1];
    float vv[8] = {v0.x, v0.y, v0.z, v0.w, v1.x, v1.y, v1.z, v1.w};
    float zz[8] = {z0.x, z0.y, z0.z, z0.w, z1.x, z1.y, z1.z, z1.w};
    float ga[8] = {gg0.x, gg0.y, gg0.z, gg0.w, gg1.x, gg1.y, gg1.z, gg1.w};
    float ba[8] = {bb0.x, bb0.y, bb0.z, bb0.w, bb1.x, bb1.y, bb1.z, bb1.w};
    float o[8];
    #pragma unroll
    for (int k = 0; k < 8; k++) {
        float sz = zz[k] / (1.f + expf(-zz[k]));
        o[k] = ((vv[k] - m) * rs * ga[k] + ba[k]) * sz;
    }
    split8_store(o, g_ahi, g_alo, (size_t)p * CC, lane);
}

// ---------------- post-LN stats (warp per row) ----------------
__global__ __launch_bounds__(256)
void k_stats() {
    int warp = threadIdx.x >> 5, lane = threadIdx.x & 31;
    int p = blockIdx.x * 8 + warp;
    const float4* row = (const float4*)(g_t + (size_t)p * CC);
    float4 v0 = row[lane * 2], v1 = row[lane * 2 + 1];
    float s  = v0.x + v0.y + v0.z + v0.w + v1.x + v1.y + v1.z + v1.w;
    float s2 = v0.x*v0.x + v0.y*v0.y + v0.z*v0.z + v0.w*v0.w
             + v1.x*v1.x + v1.y*v1.y + v1.z*v1.z + v1.w*v1.w;
    warpRed2(s, s2);
    if (lane == 0) {
        float m = s * (1.f / CC);
        g_rowm[p] = m;
        g_rowrs[p] = rsqrtf(s2 * (1.f / CC) - m * m + 1e-5f);
    }
}

// ---------------- final transpose with fused post-LN apply ----------------
__global__ void k_final_tr(float* __restrict__ out,
                           const float* __restrict__ pg, const float* __restrict__ pb) {
    __shared__ float tile[32][33];
    int b = blockIdx.z >> 4, d = blockIdx.z & 15;
    int hw0 = blockIdx.x * 32, c0 = blockIdx.y * 32;
    int tx = threadIdx.x, ty = threadIdx.y;
    int p = b * LL + (hw0 + ty) * 16 + d;
    int c = c0 + tx;
    float v = g_t[(size_t)p * CC + c];
    tile[ty][tx] = (v - g_rowm[p]) * g_rowrs[p] * pg[c] + pb[c];
    __syncthreads();
    out[((size_t)(b * CC + c0 + ty) * 16 + d) * 256 + hw0 + tx] = tile[tx][ty];
}

// ---------------- host ----------------
extern "C" void kernel_launch(void* const* d_in, const int* in_sizes, int n_in,
                              void* d_out, int out_size) {
    const float* x       = (const float*)d_in[0];
    const float* in_w    = (const float*)d_in[1];
    const float* conv_w  = (const float*)d_in[2];
    const float* conv_b  = (const float*)d_in[3];
    const float* xproj_w = (const float*)d_in[4];
    const float* dt_w    = (const float*)d_in[5];
    const float* dt_b    = (const float*)d_in[6];
    const float* A_log   = (const float*)d_in[7];
    const float* D_skip  = (const float*)d_in[8];
    const float* on_g    = (const float*)d_in[9];
    const float* on_b    = (const float*)d_in[10];
    const float* out_w   = (const float*)d_in[11];
    const float* ln1_g   = (const float*)d_in[12];
    const float* ln1_b   = (const float*)d_in[13];
    const float* post_g  = (const float*)d_in[14];
    const float* post_b  = (const float*)d_in[15];
    float* out = (float*)d_out;

    void *p_t, *p_xz, *p_dbl, *p_ahi, *p_alo, *p_whi, *p_wlo;
    cudaGetSymbolAddress(&p_t,   g_t);
    cudaGetSymbolAddress(&p_xz,  g_xz);
    cudaGetSymbolAddress(&p_dbl, g_dbl);
    cudaGetSymbolAddress(&p_ahi, g_ahi);
    cudaGetSymbolAddress(&p_alo, g_alo);
    cudaGetSymbolAddress(&p_whi, g_whi);
    cudaGetSymbolAddress(&p_wlo, g_wlo);
    const uint32_t* whi = (const uint32_t*)p_whi;
    const uint32_t* wlo = (const uint32_t*)p_wlo;

    const int SM128 = (2 * 128 * 40 + 2 * 128 * 40) * 4;   // 81920 B
    const int SM64  = (2 * 128 * 40 + 2 * 64 * 40) * 4;    // 61440 B
    static int attr_done = 0;
    if (!attr_done) {
        cudaFuncSetAttribute(k_mgemm<128>, cudaFuncAttributeMaxDynamicSharedMemorySize, SM128);
        cudaFuncSetAttribute(k_mgemm<64>,  cudaFuncAttributeMaxDynamicSharedMemorySize, SM64);
        attr_done = 1;
    }

    k_wsplit_all<<<(WTOT + 255) / 256, 256>>>(in_w, xproj_w, out_w);
    k_init_tr<<<dim3(8, 8, 32), dim3(32, 32)>>>(x);

    for (int i = 0; i < 4; i++) {
        int ori = i;  // i % 8
        k_ln1<<<1024, 256>>>(ln1_g + i * 256, ln1_b + i * 256);
        // in-proj: (8192 x 512)   [launch index 3 on i==0 -> ncu profile target]
        k_mgemm<128><<<dim3(4, 64), 256, SM128>>>(
            (const uint32_t*)p_ahi, (const uint32_t*)p_alo,
            whi + WOFF_IN(i) / 2, wlo + WOFF_IN(i) / 2,
            (float*)p_xz, 512, 512, 0);
        if (i == 0) k_prepA_all<<<4, 256>>>(A_log);
        k_conv<<<BB * 256, 256>>>(conv_w + (size_t)i * 6912, conv_b + i * 256, ori);
        // xproj: (8192 x 48), weights padded to 64 rows
        k_mgemm<64><<<dim3(1, 64), 256, SM64>>>(
            (const uint32_t*)p_ahi, (const uint32_t*)p_alo,
            whi + WOFF_XP(i) / 2, wlo + WOFF_XP(i) / 2,
            (float*)p_dbl, 48, 48, 0);
        k_scanA<<<dim3(NCH, 2, BB), 128>>>(i, dt_w + (size_t)i * 4096, dt_b + i * 256);
        k_scanB<<<32, 256>>>();
        k_scanC<<<dim3(NCH, 2, BB), 128>>>(i, dt_w + (size_t)i * 4096, dt_b + i * 256,
                                           D_skip + i * 256);
        k_gate<<<1024, 256>>>(on_g + i * 256, on_b + i * 256, ori);
        // out-proj + residual into t
        k_mgemm<128><<<dim3(2, 64), 256, SM128>>>(
            (const uint32_t*)p_ahi, (const uint32_t*)p_alo,
            whi + WOFF_OUT(i) / 2, wlo + WOFF_OUT(i) / 2,
            (float*)p_t, 256, 256, 1);
    }

    k_stats<<<1024, 256>>>();
    k_final_tr<<<dim3(8, 8, 32), dim3(32, 32)>>>(out, post_g, post_b);
}